// round 8
// baseline (speedup 1.0000x reference)
#include <cuda_runtime.h>
#include <math.h>
#include <stdint.h>

#define NB 32
#define NP 100
#define NA 25200
#define NC 80
#define EPSF 1e-7f
#define POS_THR 0.5f
#define NEG_THR 0.4f
// 4 / pi^2
#define FOUR_OVER_PI2 0.40528473456935109f

// ---------------- scratch (device globals; no allocation allowed) ----------
__device__ float              g_max_iou[NB * NA];
__device__ int                g_true_idx[NB * NA];
__device__ int                g_lowq[NB * NA];          // -1 or overriding gt index
__device__ unsigned long long g_gt[NB * NP];            // packed (iou_bits<<32)|(~anchor)
__device__ int                g_label[NB * NP];
__device__ int                g_cnt[NB];
__device__ double             g_sum[3];                 // score, cls, bbox raw sums

// ---------------- init (small tail state only; g_lowq folded into k_assign) -
__global__ void k_init() {
    int i = blockIdx.x * blockDim.x + threadIdx.x;
    if (i < NB * NP) g_gt[i] = 0ULL;
    if (i < NB)      g_cnt[i] = 0;
    if (i < 3)       g_sum[i] = 0.0;
}

// ---------------- assignment: per-anchor max/argmax + per-gt max/argmax -----
__global__ void k_assign(const float* __restrict__ bbox_true,
                         const float* __restrict__ anchors) {
    const int n = blockIdx.y;
    __shared__ float4 s_gtb[NP];
    __shared__ float  s_area[NP];
    __shared__ int    s_list[NP];
    __shared__ int    s_cnt;
    __shared__ unsigned long long s_gt[NP];

    const int tid = threadIdx.x;
    for (int p = tid; p < NP; p += blockDim.x) {
        float4 b = reinterpret_cast<const float4*>(bbox_true)[n * NP + p];
        s_gtb[p]  = b;
        s_area[p] = (b.z - b.x) * (b.w - b.y);
        s_gt[p]   = 0ULL;
    }
    __syncthreads();
    if (tid == 0) {
        int c = 0;
        for (int p = 0; p < NP; p++) {
            float4 b = s_gtb[p];
            if (b.x > 0.f || b.y > 0.f || b.z > 0.f || b.w > 0.f) s_list[c++] = p;
        }
        s_cnt = c;
    }
    __syncthreads();
    const int cnt = s_cnt;

    const int a = blockIdx.x * blockDim.x + tid;
    if (a < NA) {
        float4 ab = reinterpret_cast<const float4*>(anchors)[a];
        float aarea = (ab.z - ab.x) * (ab.w - ab.y);
        float best = -1.0f;          // masked (invalid) columns are -1 in reference
        int   bidx = 0;
        const unsigned long long alow = (unsigned long long)(0xFFFFFFFFu - (unsigned)a);
        for (int k = 0; k < cnt; k++) {
            int p = s_list[k];                 // ascending -> argmax first-wins
            float4 b = s_gtb[p];
            float iw = fminf(ab.z, b.z) - fmaxf(ab.x, b.x);
            float ih = fminf(ab.w, b.w) - fmaxf(ab.y, b.y);
            iw = fmaxf(iw, 0.f); ih = fmaxf(ih, 0.f);
            float inter = iw * ih;
            float iou = inter / (aarea + s_area[p] - inter + EPSF);
            if (iou > best) { best = iou; bidx = p; }
            if (iou > 0.f) {
                unsigned long long key =
                    ((unsigned long long)__float_as_uint(iou) << 32) | alow;
                atomicMax(&s_gt[p], key);
            }
        }
        g_max_iou[n * NA + a]  = best;
        g_true_idx[n * NA + a] = bidx;
        g_lowq[n * NA + a]     = -1;    // init here (k_scatter overwrites sparsely)
    }
    __syncthreads();
    for (int p = tid; p < NP; p += blockDim.x) {
        unsigned long long v = s_gt[p];
        if (v) atomicMax(&g_gt[n * NP + p], v);
    }
}

// ---------------- labels: argmax over one-hot rows --------------------------
__global__ void k_label(const float* __restrict__ y_true) {
    int i = blockIdx.x * blockDim.x + threadIdx.x;
    if (i >= NB * NP) return;
    const float* row = y_true + (size_t)i * NC;
    int lab = 0;
    for (int c = 0; c < NC; c++)
        if (row[c] > 0.5f) { lab = c; break; }
    g_label[i] = lab;
}

// ---------------- low-quality match scatter (serial per image = XLA order) --
__global__ void k_scatter(const float* __restrict__ bbox_true) {
    int n = threadIdx.x;
    if (n >= NB) return;
    for (int p = 0; p < NP; p++) {
        const float* b = bbox_true + (size_t)(n * NP + p) * 4;
        bool valid = (b[0] > 0.f) || (b[1] > 0.f) || (b[2] > 0.f) || (b[3] > 0.f);
        if (!valid) continue;
        unsigned long long v = g_gt[n * NP + p];
        if ((v >> 32) == 0ULL) continue;           // gt_max <= 0
        unsigned a = 0xFFFFFFFFu - (unsigned)(v & 0xFFFFFFFFu);
        g_lowq[n * NA + a] = p;                    // later p overwrites (last wins)
    }
}

// ---------------- CIoU ------------------------------------------------------
__device__ __forceinline__ float ciou(float4 t, float4 p) {
    float ix1 = fmaxf(t.x, p.x), iy1 = fmaxf(t.y, p.y);
    float ix2 = fminf(t.z, p.z), iy2 = fminf(t.w, p.w);
    float inter = fmaxf(ix2 - ix1, 0.f) * fmaxf(iy2 - iy1, 0.f);
    float wt = t.z - t.x, ht = t.w - t.y;
    float wp = p.z - p.x, hp = p.w - p.y;
    float uni = wt * ht + wp * hp - inter + EPSF;
    float iou = inter / uni;
    float cw = fmaxf(t.z, p.z) - fminf(t.x, p.x);
    float ch = fmaxf(t.w, p.w) - fminf(t.y, p.y);
    float c2 = cw * cw + ch * ch + EPSF;
    float dx = t.x + t.z - p.x - p.z;
    float dy = t.y + t.w - p.y - p.w;
    float rho2 = (dx * dx + dy * dy) * 0.25f;
    float d = atanf(wt / (ht + EPSF)) - atanf(wp / (hp + EPSF));
    float v = FOUR_OVER_PI2 * d * d;
    float alpha = v / (1.f - iou + v + EPSF);
    return 1.f - iou + rho2 / c2 + alpha * v;
}

// ---------------- losses ----------------------------------------------------
__global__ void k_loss(const float* __restrict__ conf,
                       const float* __restrict__ logit,
                       const float* __restrict__ bbox_true,
                       const float* __restrict__ bbox_pred) {
    const int n = blockIdx.y;
    const int a = blockIdx.x * blockDim.x + threadIdx.x;

    float score = 0.f, cls = 0.f, bb = 0.f;
    int cnt = 0;

    if (a < NA) {
        const int i = n * NA + a;
        float mi  = g_max_iou[i];
        int  lidx = g_lowq[i];
        bool pos = (mi >= POS_THR) || (lidx >= 0);
        bool neg = (mi < NEG_THR) && !pos;

        float p = fminf(fmaxf(conf[i], EPSF), 1.f - EPSF);
        if (pos) { score = -logf(p); cnt = 1; }
        else if (neg) { score = -logf(1.f - p); }

        if (pos) {
            int idx = (lidx >= 0) ? lidx : g_true_idx[i];
            int lab = g_label[n * NP + idx];
            const float* q = logit + (size_t)i * NC;
            float s = 0.f;
#pragma unroll 4
            for (int c = 0; c < NC; c++) {
                float qc = fminf(fmaxf(q[c], EPSF), 1.f - EPSF);
                if (c == lab) {
                    float u = 1.f - qc;
                    s += -0.25f * u * u * logf(qc);
                } else {
                    s += -0.75f * qc * qc * logf(1.f - qc);
                }
            }
            cls = s;
            float4 bt = reinterpret_cast<const float4*>(bbox_true)[n * NP + idx];
            float4 bp = reinterpret_cast<const float4*>(bbox_pred)[i];
            bb = ciou(bt, bp);
        }
    }

    // block reduce (256 threads = 8 warps)
#pragma unroll
    for (int o = 16; o; o >>= 1) {
        score += __shfl_down_sync(0xFFFFFFFFu, score, o);
        cls   += __shfl_down_sync(0xFFFFFFFFu, cls, o);
        bb    += __shfl_down_sync(0xFFFFFFFFu, bb, o);
        cnt   += __shfl_down_sync(0xFFFFFFFFu, cnt, o);
    }
    __shared__ float sw0[8], sw1[8], sw2[8];
    __shared__ int   swc[8];
    int w = threadIdx.x >> 5, l = threadIdx.x & 31;
    if (l == 0) { sw0[w] = score; sw1[w] = cls; sw2[w] = bb; swc[w] = cnt; }
    __syncthreads();
    if (threadIdx.x < 32) {
        score = (l < 8) ? sw0[l] : 0.f;
        cls   = (l < 8) ? sw1[l] : 0.f;
        bb    = (l < 8) ? sw2[l] : 0.f;
        cnt   = (l < 8) ? swc[l] : 0;
#pragma unroll
        for (int o = 4; o; o >>= 1) {
            score += __shfl_down_sync(0xFFFFFFFFu, score, o);
            cls   += __shfl_down_sync(0xFFFFFFFFu, cls, o);
            bb    += __shfl_down_sync(0xFFFFFFFFu, bb, o);
            cnt   += __shfl_down_sync(0xFFFFFFFFu, cnt, o);
        }
        if (l == 0) {
            if (score != 0.f) atomicAdd(&g_sum[0], (double)score);
            if (cls   != 0.f) atomicAdd(&g_sum[1], (double)cls);
            if (bb    != 0.f) atomicAdd(&g_sum[2], (double)bb);
            if (cnt) atomicAdd(&g_cnt[n], cnt);
        }
    }
}

// ---------------- finalize --------------------------------------------------
__global__ void k_final(float* __restrict__ out) {
    int t = threadIdx.x;
    float c = (t < NB) ? fmaxf((float)g_cnt[t], 1.f) : 0.f;
#pragma unroll
    for (int o = 16; o; o >>= 1) c += __shfl_down_sync(0xFFFFFFFFu, c, o);
    if (t == 0) {
        double avg = (double)c;
        for (int k = 0; k < 3; k++) {
            float f = (float)(g_sum[k] / avg);
            if (isnan(f) || isinf(f)) f = 0.f;
            out[k] = f;
        }
    }
}

// ---------------- launch ----------------------------------------------------
extern "C" void kernel_launch(void* const* d_in, const int* in_sizes, int n_in,
                              void* d_out, int out_size) {
    const float *y_true = nullptr, *bbox_true = nullptr, *conf = nullptr;
    const float *logit = nullptr, *bbox_pred = nullptr, *anchors = nullptr;
    for (int i = 0; i < n_in; i++) {
        switch (in_sizes[i]) {
            case NB * NP * NC: y_true    = (const float*)d_in[i]; break;  // 256000
            case NB * NP * 4:  bbox_true = (const float*)d_in[i]; break;  // 12800
            case NB * NA:      conf      = (const float*)d_in[i]; break;  // 806400
            case NB * NA * NC: logit     = (const float*)d_in[i]; break;  // 64512000
            case NB * NA * 4:  bbox_pred = (const float*)d_in[i]; break;  // 3225600
            case NA * 4:       anchors   = (const float*)d_in[i]; break;  // 100800
            default: break;
        }
    }

    const int TB = 256;
    const int ablk = (NA + TB - 1) / TB;  // 99

    k_init<<<(NB * NP + TB - 1) / TB, TB>>>();
    k_assign<<<dim3(ablk, NB), TB>>>(bbox_true, anchors);
    k_label<<<(NB * NP + TB - 1) / TB, TB>>>(y_true);
    k_scatter<<<1, NB>>>(bbox_true);
    k_loss<<<dim3(ablk, NB), TB>>>(conf, logit, bbox_true, bbox_pred);
    k_final<<<1, 32>>>((float*)d_out);
}

// round 13
// speedup vs baseline: 1.2486x; 1.2486x over previous
#include <cuda_runtime.h>
#include <math.h>
#include <stdint.h>

#define NB 32
#define NP 100
#define NA 25200
#define NC 80
#define EPSF 1e-7f
#define POS_THR 0.5f
#define NEG_THR 0.4f
// 4 / pi^2
#define FOUR_OVER_PI2 0.40528473456935109f

// ---------------- scratch (device globals; no allocation allowed) ----------
__device__ float              g_max_iou[NB * NA];
__device__ int                g_true_idx[NB * NA];
__device__ int                g_lowq[NB * NA];          // -1 or overriding gt index
__device__ unsigned long long g_gt[NB * NP];            // packed (iou_bits<<32)|(~anchor)
__device__ int                g_label[NB * NP];
__device__ int                g_cnt[NB];
__device__ double             g_sum[3];                 // score, cls, bbox raw sums

// ---------------- init (small tail state only; g_lowq folded into k_assign) -
__global__ void k_init() {
    int i = blockIdx.x * blockDim.x + threadIdx.x;
    if (i < NB * NP) g_gt[i] = 0ULL;
    if (i < NB)      g_cnt[i] = 0;
    if (i < 3)       g_sum[i] = 0.0;
}

// ---------------- assignment: per-anchor max/argmax + per-gt max/argmax -----
__global__ void k_assign(const float* __restrict__ bbox_true,
                         const float* __restrict__ anchors) {
    const int n = blockIdx.y;
    __shared__ float4 s_gtb[NP];
    __shared__ float  s_area[NP];
    __shared__ int    s_list[NP];
    __shared__ int    s_cnt;
    __shared__ unsigned long long s_gt[NP];

    const int tid = threadIdx.x;
    for (int p = tid; p < NP; p += blockDim.x) {
        float4 b = reinterpret_cast<const float4*>(bbox_true)[n * NP + p];
        s_gtb[p]  = b;
        s_area[p] = (b.z - b.x) * (b.w - b.y);
        s_gt[p]   = 0ULL;
    }
    __syncthreads();
    if (tid == 0) {
        int c = 0;
        for (int p = 0; p < NP; p++) {
            float4 b = s_gtb[p];
            if (b.x > 0.f || b.y > 0.f || b.z > 0.f || b.w > 0.f) s_list[c++] = p;
        }
        s_cnt = c;
    }
    __syncthreads();
    const int cnt = s_cnt;

    const int a = blockIdx.x * blockDim.x + tid;
    if (a < NA) {
        float4 ab = reinterpret_cast<const float4*>(anchors)[a];
        float aarea = (ab.z - ab.x) * (ab.w - ab.y);
        float best = -1.0f;          // masked (invalid) columns are -1 in reference
        int   bidx = 0;
        const unsigned long long alow = (unsigned long long)(0xFFFFFFFFu - (unsigned)a);
        for (int k = 0; k < cnt; k++) {
            int p = s_list[k];                 // ascending -> argmax first-wins
            float4 b = s_gtb[p];
            float iw = fminf(ab.z, b.z) - fmaxf(ab.x, b.x);
            float ih = fminf(ab.w, b.w) - fmaxf(ab.y, b.y);
            iw = fmaxf(iw, 0.f); ih = fmaxf(ih, 0.f);
            float inter = iw * ih;
            float iou = inter / (aarea + s_area[p] - inter + EPSF);
            if (iou > best) { best = iou; bidx = p; }
            if (iou > 0.f) {
                unsigned long long key =
                    ((unsigned long long)__float_as_uint(iou) << 32) | alow;
                atomicMax(&s_gt[p], key);
            }
        }
        g_max_iou[n * NA + a]  = best;
        g_true_idx[n * NA + a] = bidx;
        g_lowq[n * NA + a]     = -1;    // init here (k_scatter overwrites sparsely)
    }
    __syncthreads();
    for (int p = tid; p < NP; p += blockDim.x) {
        unsigned long long v = s_gt[p];
        if (v) atomicMax(&g_gt[n * NP + p], v);
    }
}

// ---------------- labels: argmax over one-hot rows --------------------------
__global__ void k_label(const float* __restrict__ y_true) {
    int i = blockIdx.x * blockDim.x + threadIdx.x;
    if (i >= NB * NP) return;
    const float* row = y_true + (size_t)i * NC;
    int lab = 0;
    for (int c = 0; c < NC; c++)
        if (row[c] > 0.5f) { lab = c; break; }
    g_label[i] = lab;
}

// ---------------- low-quality match scatter ---------------------------------
// Reference semantics: serial ascending-p loop, duplicate anchors -> last p
// wins.  Last-wins under ascending order == max p, so a parallel atomicMax
// over p is bit-identical (g_lowq pre-initialized to -1 in k_assign).
__global__ void k_scatter(const float* __restrict__ bbox_true) {
    int i = blockIdx.x * blockDim.x + threadIdx.x;   // i = n*NP + p
    if (i >= NB * NP) return;
    int n = i / NP;
    int p = i - n * NP;
    float4 b = reinterpret_cast<const float4*>(bbox_true)[i];
    bool valid = (b.x > 0.f) || (b.y > 0.f) || (b.z > 0.f) || (b.w > 0.f);
    if (!valid) return;
    unsigned long long v = g_gt[i];
    if ((v >> 32) == 0ULL) return;                   // gt_max <= 0
    unsigned a = 0xFFFFFFFFu - (unsigned)(v & 0xFFFFFFFFu);
    atomicMax(&g_lowq[n * NA + a], p);               // last-wins == max p
}

// ---------------- CIoU ------------------------------------------------------
__device__ __forceinline__ float ciou(float4 t, float4 p) {
    float ix1 = fmaxf(t.x, p.x), iy1 = fmaxf(t.y, p.y);
    float ix2 = fminf(t.z, p.z), iy2 = fminf(t.w, p.w);
    float inter = fmaxf(ix2 - ix1, 0.f) * fmaxf(iy2 - iy1, 0.f);
    float wt = t.z - t.x, ht = t.w - t.y;
    float wp = p.z - p.x, hp = p.w - p.y;
    float uni = wt * ht + wp * hp - inter + EPSF;
    float iou = inter / uni;
    float cw = fmaxf(t.z, p.z) - fminf(t.x, p.x);
    float ch = fmaxf(t.w, p.w) - fminf(t.y, p.y);
    float c2 = cw * cw + ch * ch + EPSF;
    float dx = t.x + t.z - p.x - p.z;
    float dy = t.y + t.w - p.y - p.w;
    float rho2 = (dx * dx + dy * dy) * 0.25f;
    float d = atanf(wt / (ht + EPSF)) - atanf(wp / (hp + EPSF));
    float v = FOUR_OVER_PI2 * d * d;
    float alpha = v / (1.f - iou + v + EPSF);
    return 1.f - iou + rho2 / c2 + alpha * v;
}

// ---------------- losses ----------------------------------------------------
__global__ void k_loss(const float* __restrict__ conf,
                       const float* __restrict__ logit,
                       const float* __restrict__ bbox_true,
                       const float* __restrict__ bbox_pred) {
    const int n = blockIdx.y;
    const int a = blockIdx.x * blockDim.x + threadIdx.x;

    float score = 0.f, cls = 0.f, bb = 0.f;
    int cnt = 0;

    if (a < NA) {
        const int i = n * NA + a;
        float mi  = g_max_iou[i];
        int  lidx = g_lowq[i];
        bool pos = (mi >= POS_THR) || (lidx >= 0);
        bool neg = (mi < NEG_THR) && !pos;

        float p = fminf(fmaxf(conf[i], EPSF), 1.f - EPSF);
        if (pos) { score = -logf(p); cnt = 1; }
        else if (neg) { score = -logf(1.f - p); }

        if (pos) {
            int idx = (lidx >= 0) ? lidx : g_true_idx[i];
            int lab = g_label[n * NP + idx];
            const float* q = logit + (size_t)i * NC;
            float s = 0.f;
#pragma unroll 4
            for (int c = 0; c < NC; c++) {
                float qc = fminf(fmaxf(q[c], EPSF), 1.f - EPSF);
                if (c == lab) {
                    float u = 1.f - qc;
                    s += -0.25f * u * u * logf(qc);
                } else {
                    s += -0.75f * qc * qc * logf(1.f - qc);
                }
            }
            cls = s;
            float4 bt = reinterpret_cast<const float4*>(bbox_true)[n * NP + idx];
            float4 bp = reinterpret_cast<const float4*>(bbox_pred)[i];
            bb = ciou(bt, bp);
        }
    }

    // block reduce (256 threads = 8 warps)
#pragma unroll
    for (int o = 16; o; o >>= 1) {
        score += __shfl_down_sync(0xFFFFFFFFu, score, o);
        cls   += __shfl_down_sync(0xFFFFFFFFu, cls, o);
        bb    += __shfl_down_sync(0xFFFFFFFFu, bb, o);
        cnt   += __shfl_down_sync(0xFFFFFFFFu, cnt, o);
    }
    __shared__ float sw0[8], sw1[8], sw2[8];
    __shared__ int   swc[8];
    int w = threadIdx.x >> 5, l = threadIdx.x & 31;
    if (l == 0) { sw0[w] = score; sw1[w] = cls; sw2[w] = bb; swc[w] = cnt; }
    __syncthreads();
    if (threadIdx.x < 32) {
        score = (l < 8) ? sw0[l] : 0.f;
        cls   = (l < 8) ? sw1[l] : 0.f;
        bb    = (l < 8) ? sw2[l] : 0.f;
        cnt   = (l < 8) ? swc[l] : 0;
#pragma unroll
        for (int o = 4; o; o >>= 1) {
            score += __shfl_down_sync(0xFFFFFFFFu, score, o);
            cls   += __shfl_down_sync(0xFFFFFFFFu, cls, o);
            bb    += __shfl_down_sync(0xFFFFFFFFu, bb, o);
            cnt   += __shfl_down_sync(0xFFFFFFFFu, cnt, o);
        }
        if (l == 0) {
            if (score != 0.f) atomicAdd(&g_sum[0], (double)score);
            if (cls   != 0.f) atomicAdd(&g_sum[1], (double)cls);
            if (bb    != 0.f) atomicAdd(&g_sum[2], (double)bb);
            if (cnt) atomicAdd(&g_cnt[n], cnt);
        }
    }
}

// ---------------- finalize --------------------------------------------------
__global__ void k_final(float* __restrict__ out) {
    int t = threadIdx.x;
    float c = (t < NB) ? fmaxf((float)g_cnt[t], 1.f) : 0.f;
#pragma unroll
    for (int o = 16; o; o >>= 1) c += __shfl_down_sync(0xFFFFFFFFu, c, o);
    if (t == 0) {
        double avg = (double)c;
        for (int k = 0; k < 3; k++) {
            float f = (float)(g_sum[k] / avg);
            if (isnan(f) || isinf(f)) f = 0.f;
            out[k] = f;
        }
    }
}

// ---------------- launch ----------------------------------------------------
extern "C" void kernel_launch(void* const* d_in, const int* in_sizes, int n_in,
                              void* d_out, int out_size) {
    const float *y_true = nullptr, *bbox_true = nullptr, *conf = nullptr;
    const float *logit = nullptr, *bbox_pred = nullptr, *anchors = nullptr;
    for (int i = 0; i < n_in; i++) {
        switch (in_sizes[i]) {
            case NB * NP * NC: y_true    = (const float*)d_in[i]; break;  // 256000
            case NB * NP * 4:  bbox_true = (const float*)d_in[i]; break;  // 12800
            case NB * NA:      conf      = (const float*)d_in[i]; break;  // 806400
            case NB * NA * NC: logit     = (const float*)d_in[i]; break;  // 64512000
            case NB * NA * 4:  bbox_pred = (const float*)d_in[i]; break;  // 3225600
            case NA * 4:       anchors   = (const float*)d_in[i]; break;  // 100800
            default: break;
        }
    }

    const int TB = 256;
    const int ablk = (NA + TB - 1) / TB;  // 99

    k_init<<<(NB * NP + TB - 1) / TB, TB>>>();
    k_assign<<<dim3(ablk, NB), TB>>>(bbox_true, anchors);
    k_label<<<(NB * NP + TB - 1) / TB, TB>>>(y_true);
    k_scatter<<<(NB * NP + TB - 1) / TB, TB>>>(bbox_true);
    k_loss<<<dim3(ablk, NB), TB>>>(conf, logit, bbox_true, bbox_pred);
    k_final<<<1, 32>>>((float*)d_out);
}

// round 16
// speedup vs baseline: 1.4869x; 1.1909x over previous
#include <cuda_runtime.h>
#include <math.h>
#include <stdint.h>

#define NB 32
#define NP 100
#define NA 25200
#define NC 80
#define EPSF 1e-7f
#define POS_THR 0.5f
#define NEG_THR 0.4f
#define FOUR_OVER_PI2 0.40528473456935109f

// k_assign geometry: 2 anchors per thread
#define ATB 256                 // threads per block
#define APB (ATB * 2)           // anchors per block = 512
#define ABLK ((NA + APB - 1) / APB)   // 50
#define LBLK ((NA + 255) / 256)       // 99 (k_loss)

// ---------------- scratch (device globals; no allocation allowed) ----------
__device__ float              g_max_iou[NB * NA];
__device__ int                g_true_idx[NB * NA];
__device__ int                g_lowq[NB * NA];          // -1 or overriding gt index
__device__ unsigned long long g_gt[NB * NP];            // packed (iou_bits<<32)|(~anchor)
__device__ int                g_label[NB * NP];
__device__ int                g_cnt[NB];
__device__ double             g_sum[3];                 // score, cls, bbox raw sums
__device__ unsigned int       g_done1;                  // k_assign completion ticket
__device__ unsigned int       g_done2;                  // k_loss completion ticket

// ---------------- init + labels (fused small kernel) ------------------------
__global__ void k_init(const float* __restrict__ y_true) {
    int i = blockIdx.x * blockDim.x + threadIdx.x;
    if (i < NB * NP) {
        g_gt[i] = 0ULL;
        const float* row = y_true + (size_t)i * NC;
        int lab = 0;
        for (int c = 0; c < NC; c++)
            if (row[c] > 0.5f) { lab = c; break; }
        g_label[i] = lab;
    }
    if (i < NB) g_cnt[i] = 0;
    if (i < 3)  g_sum[i] = 0.0;
    if (i == 0) { g_done1 = 0u; g_done2 = 0u; }
}

// ---------------- assignment + fused low-quality scatter (last block) -------
__global__ void k_assign(const float* __restrict__ bbox_true,
                         const float* __restrict__ anchors) {
    const int n = blockIdx.y;
    __shared__ float4 s_gtb[NP];
    __shared__ float  s_area[NP];
    __shared__ int    s_list[NP];
    __shared__ int    s_cnt;
    __shared__ unsigned long long s_gt[NP];
    __shared__ bool   s_last;

    const int tid = threadIdx.x;
    for (int p = tid; p < NP; p += ATB) {
        float4 b = reinterpret_cast<const float4*>(bbox_true)[n * NP + p];
        s_gtb[p]  = b;
        s_area[p] = (b.z - b.x) * (b.w - b.y);
        s_gt[p]   = 0ULL;
    }
    __syncthreads();
    if (tid == 0) {
        int c = 0;
        for (int p = 0; p < NP; p++) {
            float4 b = s_gtb[p];
            if (b.x > 0.f || b.y > 0.f || b.z > 0.f || b.w > 0.f) s_list[c++] = p;
        }
        s_cnt = c;
    }
    __syncthreads();
    const int cnt = s_cnt;

    const int a0 = blockIdx.x * APB + tid;
    const int a1 = a0 + ATB;
    const bool v0 = (a0 < NA), v1 = (a1 < NA);

    float4 ab0 = v0 ? reinterpret_cast<const float4*>(anchors)[a0] : make_float4(0, 0, 0, 0);
    float4 ab1 = v1 ? reinterpret_cast<const float4*>(anchors)[a1] : make_float4(0, 0, 0, 0);
    float aarea0 = (ab0.z - ab0.x) * (ab0.w - ab0.y);
    float aarea1 = (ab1.z - ab1.x) * (ab1.w - ab1.y);
    float best0 = -1.f, best1 = -1.f;
    int   bidx0 = 0,    bidx1 = 0;
    const unsigned long long alow0 = (unsigned long long)(0xFFFFFFFFu - (unsigned)a0);
    const unsigned long long alow1 = (unsigned long long)(0xFFFFFFFFu - (unsigned)a1);

    for (int k = 0; k < cnt; k++) {
        int p = s_list[k];                       // ascending -> argmax first-wins
        float4 b  = s_gtb[p];
        float  ar = s_area[p];

        // anchor 0
        float iw0 = fmaxf(fminf(ab0.z, b.z) - fmaxf(ab0.x, b.x), 0.f);
        float ih0 = fmaxf(fminf(ab0.w, b.w) - fmaxf(ab0.y, b.y), 0.f);
        float inter0 = iw0 * ih0;
        // anchor 1
        float iw1 = fmaxf(fminf(ab1.z, b.z) - fmaxf(ab1.x, b.x), 0.f);
        float ih1 = fmaxf(fminf(ab1.w, b.w) - fmaxf(ab1.y, b.y), 0.f);
        float inter1 = iw1 * ih1;

        // inter==0  ->  iou = 0/(positive den) = +0.0 exactly: skip the divide
        float iou0 = 0.f, iou1 = 0.f;
        if (inter0 > 0.f) iou0 = inter0 / (aarea0 + ar - inter0 + EPSF);
        if (inter1 > 0.f) iou1 = inter1 / (aarea1 + ar - inter1 + EPSF);

        if (v0 && iou0 > best0) { best0 = iou0; bidx0 = p; }
        if (v1 && iou1 > best1) { best1 = iou1; bidx1 = p; }

        // per-gt argmax key; reference only distinguishes iou > 0
        unsigned long long key = 0ULL;
        if (v0 && iou0 > 0.f)
            key = ((unsigned long long)__float_as_uint(iou0) << 32) | alow0;
        if (v1 && iou1 > 0.f) {
            unsigned long long k1 =
                ((unsigned long long)__float_as_uint(iou1) << 32) | alow1;
            if (k1 > key) key = k1;
        }
        if (key) {
            // racy monotone prefilter: skip atomic when it cannot improve
            unsigned long long cur = *(volatile unsigned long long*)&s_gt[p];
            if (key > cur) atomicMax(&s_gt[p], key);
        }
    }

    if (v0) {
        g_max_iou[n * NA + a0]  = best0;
        g_true_idx[n * NA + a0] = bidx0;
        g_lowq[n * NA + a0]     = -1;
    }
    if (v1) {
        g_max_iou[n * NA + a1]  = best1;
        g_true_idx[n * NA + a1] = bidx1;
        g_lowq[n * NA + a1]     = -1;
    }
    __syncthreads();
    for (int p = tid; p < NP; p += ATB) {
        unsigned long long v = s_gt[p];
        if (v) atomicMax(&g_gt[n * NP + p], v);
    }

    // ----- fused scatter: last block to finish does it for all images ------
    __threadfence();
    __syncthreads();
    if (tid == 0)
        s_last = (atomicAdd(&g_done1, 1u) == (unsigned)(ABLK * NB) - 1u);
    __syncthreads();
    if (s_last) {
        __threadfence();
        // serial-ascending-p last-wins == max p -> atomicMax (bit-identical)
        for (int i = tid; i < NB * NP; i += ATB) {
            int nn = i / NP;
            int p  = i - nn * NP;
            float4 b = reinterpret_cast<const float4*>(bbox_true)[i];
            bool valid = (b.x > 0.f) || (b.y > 0.f) || (b.z > 0.f) || (b.w > 0.f);
            if (!valid) continue;
            unsigned long long v = g_gt[i];
            if ((v >> 32) == 0ULL) continue;           // gt_max <= 0
            unsigned a = 0xFFFFFFFFu - (unsigned)(v & 0xFFFFFFFFu);
            atomicMax(&g_lowq[nn * NA + a], p);
        }
    }
}

// ---------------- CIoU ------------------------------------------------------
__device__ __forceinline__ float ciou(float4 t, float4 p) {
    float ix1 = fmaxf(t.x, p.x), iy1 = fmaxf(t.y, p.y);
    float ix2 = fminf(t.z, p.z), iy2 = fminf(t.w, p.w);
    float inter = fmaxf(ix2 - ix1, 0.f) * fmaxf(iy2 - iy1, 0.f);
    float wt = t.z - t.x, ht = t.w - t.y;
    float wp = p.z - p.x, hp = p.w - p.y;
    float uni = wt * ht + wp * hp - inter + EPSF;
    float iou = inter / uni;
    float cw = fmaxf(t.z, p.z) - fminf(t.x, p.x);
    float ch = fmaxf(t.w, p.w) - fminf(t.y, p.y);
    float c2 = cw * cw + ch * ch + EPSF;
    float dx = t.x + t.z - p.x - p.z;
    float dy = t.y + t.w - p.y - p.w;
    float rho2 = (dx * dx + dy * dy) * 0.25f;
    float d = atanf(wt / (ht + EPSF)) - atanf(wp / (hp + EPSF));
    float v = FOUR_OVER_PI2 * d * d;
    float alpha = v / (1.f - iou + v + EPSF);
    return 1.f - iou + rho2 / c2 + alpha * v;
}

// ---------------- losses + fused finalize (last block) ----------------------
__global__ void k_loss(const float* __restrict__ conf,
                       const float* __restrict__ logit,
                       const float* __restrict__ bbox_true,
                       const float* __restrict__ bbox_pred,
                       float* __restrict__ out) {
    const int n = blockIdx.y;
    const int a = blockIdx.x * blockDim.x + threadIdx.x;

    float score = 0.f, cls = 0.f, bb = 0.f;
    int cnt = 0;

    if (a < NA) {
        const int i = n * NA + a;
        float mi  = g_max_iou[i];
        int  lidx = g_lowq[i];
        bool pos = (mi >= POS_THR) || (lidx >= 0);
        bool neg = (mi < NEG_THR) && !pos;

        float p = fminf(fmaxf(conf[i], EPSF), 1.f - EPSF);
        if (pos) { score = -logf(p); cnt = 1; }
        else if (neg) { score = -logf(1.f - p); }

        if (pos) {
            int idx = (lidx >= 0) ? lidx : g_true_idx[i];
            int lab = g_label[n * NP + idx];
            const float* q = logit + (size_t)i * NC;
            float s = 0.f;
#pragma unroll 4
            for (int c = 0; c < NC; c++) {
                float qc = fminf(fmaxf(q[c], EPSF), 1.f - EPSF);
                if (c == lab) {
                    float u = 1.f - qc;
                    s += -0.25f * u * u * logf(qc);
                } else {
                    s += -0.75f * qc * qc * logf(1.f - qc);
                }
            }
            cls = s;
            float4 bt = reinterpret_cast<const float4*>(bbox_true)[n * NP + idx];
            float4 bp = reinterpret_cast<const float4*>(bbox_pred)[i];
            bb = ciou(bt, bp);
        }
    }

    // block reduce (256 threads = 8 warps)
#pragma unroll
    for (int o = 16; o; o >>= 1) {
        score += __shfl_down_sync(0xFFFFFFFFu, score, o);
        cls   += __shfl_down_sync(0xFFFFFFFFu, cls, o);
        bb    += __shfl_down_sync(0xFFFFFFFFu, bb, o);
        cnt   += __shfl_down_sync(0xFFFFFFFFu, cnt, o);
    }
    __shared__ float sw0[8], sw1[8], sw2[8];
    __shared__ int   swc[8];
    __shared__ bool  s_last;
    int w = threadIdx.x >> 5, l = threadIdx.x & 31;
    if (l == 0) { sw0[w] = score; sw1[w] = cls; sw2[w] = bb; swc[w] = cnt; }
    __syncthreads();
    if (threadIdx.x < 32) {
        score = (l < 8) ? sw0[l] : 0.f;
        cls   = (l < 8) ? sw1[l] : 0.f;
        bb    = (l < 8) ? sw2[l] : 0.f;
        cnt   = (l < 8) ? swc[l] : 0;
#pragma unroll
        for (int o = 4; o; o >>= 1) {
            score += __shfl_down_sync(0xFFFFFFFFu, score, o);
            cls   += __shfl_down_sync(0xFFFFFFFFu, cls, o);
            bb    += __shfl_down_sync(0xFFFFFFFFu, bb, o);
            cnt   += __shfl_down_sync(0xFFFFFFFFu, cnt, o);
        }
        if (l == 0) {
            if (score != 0.f) atomicAdd(&g_sum[0], (double)score);
            if (cls   != 0.f) atomicAdd(&g_sum[1], (double)cls);
            if (bb    != 0.f) atomicAdd(&g_sum[2], (double)bb);
            if (cnt) atomicAdd(&g_cnt[n], cnt);
        }
    }

    // ----- fused finalize: last block to finish writes the output ----------
    __threadfence();
    __syncthreads();
    if (threadIdx.x == 0)
        s_last = (atomicAdd(&g_done2, 1u) == (unsigned)(LBLK * NB) - 1u);
    __syncthreads();
    if (s_last && threadIdx.x < 32) {
        __threadfence();
        int t = threadIdx.x;
        float c = (t < NB) ? fmaxf((float)g_cnt[t], 1.f) : 0.f;
#pragma unroll
        for (int o = 16; o; o >>= 1) c += __shfl_down_sync(0xFFFFFFFFu, c, o);
        if (t == 0) {
            double avg = (double)c;
            for (int k = 0; k < 3; k++) {
                float f = (float)(g_sum[k] / avg);
                if (isnan(f) || isinf(f)) f = 0.f;
                out[k] = f;
            }
        }
    }
}

// ---------------- launch ----------------------------------------------------
extern "C" void kernel_launch(void* const* d_in, const int* in_sizes, int n_in,
                              void* d_out, int out_size) {
    const float *y_true = nullptr, *bbox_true = nullptr, *conf = nullptr;
    const float *logit = nullptr, *bbox_pred = nullptr, *anchors = nullptr;
    for (int i = 0; i < n_in; i++) {
        switch (in_sizes[i]) {
            case NB * NP * NC: y_true    = (const float*)d_in[i]; break;  // 256000
            case NB * NP * 4:  bbox_true = (const float*)d_in[i]; break;  // 12800
            case NB * NA:      conf      = (const float*)d_in[i]; break;  // 806400
            case NB * NA * NC: logit     = (const float*)d_in[i]; break;  // 64512000
            case NB * NA * 4:  bbox_pred = (const float*)d_in[i]; break;  // 3225600
            case NA * 4:       anchors   = (const float*)d_in[i]; break;  // 100800
            default: break;
        }
    }

    k_init<<<(NB * NP + 255) / 256, 256>>>(y_true);
    k_assign<<<dim3(ABLK, NB), ATB>>>(bbox_true, anchors);
    k_loss<<<dim3(LBLK, NB), 256>>>(conf, logit, bbox_true, bbox_pred,
                                    (float*)d_out);
}